// round 12
// baseline (speedup 1.0000x reference)
#include <cuda_runtime.h>

#define G_N 8192
#define IMG_W 512
#define IMG_H 512
#define TILE_W 32
#define TILE_H 16
#define TX_N (IMG_W / TILE_W)     // 16
#define TY_N (IMG_H / TILE_H)     // 32
#define N_TILES (TX_N * TY_N)     // 512
#define NWORDS (G_N / 32)         // 256 bitmap words per tile
#define TPB 256
#define CH 512                    // raster staging chunk (entries)
#define SORT_TPB 512
#define SORT_WPB (SORT_TPB / 32)  // 16 warps per block
#define SORT_BLOCKS (G_N / SORT_WPB)                 // 512 (1 gaussian/warp)
#define CLR_PER_BLK (N_TILES * NWORDS / 4 / SORT_BLOCKS)   // 64 uint4 per block

// Sorted (by depth) gaussian data, raster-ready layout.
__device__ float4 d_A[G_N];              // mx, my, 0.5*a, b
__device__ float4 d_B[G_N];              // 0.5*c, sigma_max=ln(255*op), op, col.r
__device__ float2 d_C[G_N];              // col.g, col.b
__device__ float4 d_bbox[G_N];           // x0, y0, x1, y1
// Per-tile rank bitmaps: bit r set => sorted gaussian r overlaps the tile.
__device__ unsigned d_bits[N_TILES * NWORDS];   // 512 KB

// ---------------------------------------------------------------------------
// Kernel 1: clear bitmaps + stable rank-sort by depth + gather + bbox.
// 512 blocks x 512 threads, ONE gaussian per warp (occupancy was the R11
// limiter at 256 blocks: grid-resident warps, not instructions, bound it).
// Split comparator: j<i: kj<=ki ; j>i: kj<ki ; boundary t==tb: composite.
// Reproduces argsort(stable=True) exactly (positive floats -> monotone bits).
// ---------------------------------------------------------------------------
__global__ __launch_bounds__(SORT_TPB) void sort_gather_kernel(
    const float* __restrict__ means2d,
    const float* __restrict__ conics,
    const float* __restrict__ colors,
    const float* __restrict__ opac,
    const float* __restrict__ depths)
{
    __shared__ uint2 s_k[G_N / 2];   // 32 KB
    const int tid  = threadIdx.x;
    const int warp = tid >> 5, lane = tid & 31;

    // clear this block's slice of the bitmap (64 uint4 = 1KB per block)
    if (tid < CLR_PER_BLK)
        ((uint4*)d_bits)[blockIdx.x * CLR_PER_BLK + tid] = make_uint4(0u, 0u, 0u, 0u);

    const uint2* dbits = (const uint2*)depths;
    for (int j = tid; j < G_N / 2; j += SORT_TPB)
        s_k[j] = dbits[j];
    __syncthreads();

    const int i = blockIdx.x * SORT_WPB + warp;
    const unsigned ki = ((const unsigned*)s_k)[i];
    const int tb = i >> 6;           // boundary iteration

    int cnt = 0;
#pragma unroll 4
    for (int t = 0; t < tb; ++t) {                 // j < i : kj <= ki
        const uint2 kj = s_k[t * 32 + lane];
        cnt += (kj.x <= ki);
        cnt += (kj.y <= ki);
    }
    {   // boundary iteration: full composite comparator
        const int j2 = tb * 32 + lane;
        const uint2 kj = s_k[j2];
        const int j = 2 * j2;
        cnt += (kj.x < ki) || ((kj.x == ki) && (j     < i));
        cnt += (kj.y < ki) || ((kj.y == ki) && (j + 1 < i));
    }
#pragma unroll 4
    for (int t = tb + 1; t < G_N / 64; ++t) {      // j > i : kj < ki
        const uint2 kj = s_k[t * 32 + lane];
        cnt += (kj.x < ki);
        cnt += (kj.y < ki);
    }
    const int r = __reduce_add_sync(0xffffffffu, cnt);

    if (lane == 0) {
        const float mx = means2d[2 * i];
        const float my = means2d[2 * i + 1];
        const float a  = conics[3 * i];
        const float b  = conics[3 * i + 1];
        const float c  = conics[3 * i + 2];
        const float op = opac[i];

        // alpha = op*exp(-sigma) >= 1/255  <=>  sigma <= ln(255*op) = smax
        const float smax = logf(op * 255.0f);
        const float det  = a * c - b * b;

        d_A[r] = make_float4(mx, my, 0.5f * a, b);
        d_B[r] = make_float4(0.5f * c, smax, op, colors[3 * i]);
        d_C[r] = make_float2(colors[3 * i + 1], colors[3 * i + 2]);

        float4 bb;
        if (smax > 0.0f && det > 0.0f) {
            const float rx = sqrtf(fmaxf(0.0f, 2.0f * smax * c / det)) * 1.001f + 0.01f;
            const float ry = sqrtf(fmaxf(0.0f, 2.0f * smax * a / det)) * 1.001f + 0.01f;
            bb = make_float4(mx - rx, my - ry, mx + rx, my + ry);
        } else {
            bb = make_float4(1e9f, 1e9f, -1e9f, -1e9f);
        }
        d_bbox[r] = bb;
    }
}

// ---------------------------------------------------------------------------
// Exact (conservative) ellipse-vs-rect: keep iff min over rect of
// sigma(p) = A2*dx^2 + b*dx*dy + C2*dy^2 is <= smax (+margin).
// ---------------------------------------------------------------------------
__device__ __forceinline__ bool ellipse_hits_rect(
    float mx, float my, float A2, float b, float C2, float smax,
    float X0, float X1, float Y0, float Y1)
{
    if (mx >= X0 && mx <= X1 && my >= Y0 && my <= Y1) return true;
    const float dx0 = X0 - mx, dx1 = X1 - mx;
    const float dy0 = Y0 - my, dy1 = Y1 - my;
    const float fy = __fdividef(-b, 2.0f * C2);
    const float fx = __fdividef(-b, 2.0f * A2);

    float q = 3.4e38f;
    {   const float y = fminf(fmaxf(fy * dx0, dy0), dy1);
        q = fminf(q, A2 * dx0 * dx0 + b * dx0 * y + C2 * y * y); }
    {   const float y = fminf(fmaxf(fy * dx1, dy0), dy1);
        q = fminf(q, A2 * dx1 * dx1 + b * dx1 * y + C2 * y * y); }
    {   const float x = fminf(fmaxf(fx * dy0, dx0), dx1);
        q = fminf(q, A2 * x * x + b * x * dy0 + C2 * dy0 * dy0); }
    {   const float x = fminf(fmaxf(fx * dy1, dx0), dx1);
        q = fminf(q, A2 * x * x + b * x * dy1 + C2 * dy1 * dy1); }
    return q <= smax + 1e-2f;    // conservative margin (over-keep only)
}

// ---------------------------------------------------------------------------
// Kernel 2: binning over 32x16 tiles. 8 lanes per gaussian (4 gaussians per
// warp); lanes split the covered tile range. atomicOr -> deterministic.
// ---------------------------------------------------------------------------
__global__ __launch_bounds__(TPB) void binning_kernel()
{
    const int r   = (blockIdx.x * (TPB / 32) + (threadIdx.x >> 5)) * 4
                  + ((threadIdx.x >> 3) & 3);
    const int sub = threadIdx.x & 7;

    const float4 bb = d_bbox[r];
    if (bb.x > bb.z) return;

    const int tx0 = max(0, __float2int_rd((bb.x - 0.5f) * (1.0f / 32.0f)));
    const int tx1 = min(TX_N - 1, __float2int_rd((bb.z - 0.5f) * (1.0f / 32.0f)));
    const int ty0 = max(0, __float2int_rd((bb.y - 0.5f) * (1.0f / 16.0f)));
    const int ty1 = min(TY_N - 1, __float2int_rd((bb.w - 0.5f) * (1.0f / 16.0f)));
    if (tx1 < tx0 || ty1 < ty0) return;

    const int W = tx1 - tx0 + 1;
    const int n = W * (ty1 - ty0 + 1);

    const float4 A = d_A[r];    // mx, my, a/2, b
    const float4 B = d_B[r];    // c/2, smax, op, col.r

    for (int t = sub; t < n; t += 8) {
        const int tx = tx0 + t % W;
        const int ty = ty0 + t / W;
        const float X0 = (float)(tx * TILE_W) + 0.5f;
        const float Y0 = (float)(ty * TILE_H) + 0.5f;
        if (ellipse_hits_rect(A.x, A.y, A.z, A.w, B.x, B.y,
                              X0, X0 + (float)(TILE_W - 1),
                              Y0, Y0 + (float)(TILE_H - 1))) {
            const int tile = ty * TX_N + tx;
            atomicOr(&d_bits[tile * NWORDS + (r >> 5)], 1u << (r & 31));
        }
    }
}

// ---------------------------------------------------------------------------
// Kernel 3: raster. One 32x16 tile per block, 256 threads, 2 px/thread:
// pixel (x, y) and (x, y+8) share the column -> dx, 0.5a*dx^2 and b*dx are
// computed once per rank for both pixels (~halves per-pixel eval cost).
// Phase 1: bitmap -> compact uint16 rank list (ascending rank == depth order).
// Phase 2: 512-entry chunks staged to smem, composite from broadcast LDS;
// warp exits via __all_sync when all its 64 pixels reach T < 1e-4 (exact).
// ---------------------------------------------------------------------------
__global__ __launch_bounds__(TPB) void raster_kernel(float* __restrict__ out)
{
    const int tileX = blockIdx.x, tileY = blockIdx.y;
    const int tileI = tileY * TX_N + tileX;
    const int tid   = threadIdx.x;
    const int warp  = tid >> 5, lane = tid & 31;
    const int lx    = tid & (TILE_W - 1);      // 0..31
    const int ly    = tid >> 5;                // 0..7
    const float px  = (float)(tileX * TILE_W + lx) + 0.5f;
    const float py1 = (float)(tileY * TILE_H + ly) + 0.5f;

    __shared__ unsigned short s_list[G_N];   // 16 KB
    __shared__ float4 s_A[CH];               // 8 KB
    __shared__ float4 s_B[CH];               // 8 KB
    __shared__ float2 s_C[CH];               // 4 KB
    __shared__ int s_wsum[8];
    __shared__ int s_cnt;

    // ---- Phase 1: build list ----
    const unsigned w = d_bits[tileI * NWORDS + tid];
    const int c = __popc(w);

    int incl = c;
#pragma unroll
    for (int o = 1; o < 32; o <<= 1) {
        const int v = __shfl_up_sync(0xffffffffu, incl, o);
        if (lane >= o) incl += v;
    }
    if (lane == 31) s_wsum[warp] = incl;
    __syncthreads();
    int base = 0;
#pragma unroll
    for (int k = 0; k < 8; ++k)
        if (k < warp) base += s_wsum[k];
    if (tid == 0) {
        int tot = 0;
#pragma unroll
        for (int k = 0; k < 8; ++k) tot += s_wsum[k];
        s_cnt = tot;
    }
    int ofs = base + incl - c;
    unsigned bits = w;
    const int rbase = tid << 5;
    while (bits) {
        const int rb = __ffs(bits) - 1;
        bits &= bits - 1;
        s_list[ofs++] = (unsigned short)(rbase + rb);
    }
    __syncthreads();
    const int cnt = s_cnt;

    // ---- Phase 2: chunked stage + composite (2 px/thread) ----
    float T1 = 1.0f, T2 = 1.0f;
    float r1 = 0.f, g1 = 0.f, b1 = 0.f;
    float r2 = 0.f, g2 = 0.f, b2 = 0.f;
    bool done1 = false, done2 = false;

    for (int c0 = 0; c0 < cnt; c0 += CH) {
        const int n = min(CH, cnt - c0);
        for (int k = tid; k < n; k += TPB) {
            const int r = s_list[c0 + k];
            s_A[k] = d_A[r];
            s_B[k] = d_B[r];
            s_C[k] = d_C[r];
        }
        __syncthreads();

#pragma unroll 1
        for (int j = 0; j < n; ++j) {
            if (!(done1 && done2)) {
                const float4 A = s_A[j];       // broadcast LDS
                const float4 B = s_B[j];
                const float dx  = px  - A.x;
                const float dy1 = py1 - A.y;
                const float dy2 = dy1 + 8.0f;
                const float u = A.z * dx * dx;     // (a/2)dx^2 (shared)
                const float v = A.w * dx;          // b*dx (shared)
                const float s1 = fmaf(B.x * dy1, dy1, fmaf(v, dy1, u));
                const float s2 = fmaf(B.x * dy2, dy2, fmaf(v, dy2, u));
                const bool p1 = (s1 >= 0.0f) && (s1 <= B.y) && !done1;
                const bool p2 = (s2 >= 0.0f) && (s2 <= B.y) && !done2;
                if (p1 | p2) {
                    const float2 C = s_C[j];
                    if (p1) {
                        const float alpha = fminf(0.99f, B.z * __expf(-s1));
                        const float wgt = alpha * T1;
                        r1 += wgt * B.w; g1 += wgt * C.x; b1 += wgt * C.y;
                        T1 *= (1.0f - alpha);
                        done1 = (T1 < 1e-4f);
                    }
                    if (p2) {
                        const float alpha = fminf(0.99f, B.z * __expf(-s2));
                        const float wgt = alpha * T2;
                        r2 += wgt * B.w; g2 += wgt * C.x; b2 += wgt * C.y;
                        T2 *= (1.0f - alpha);
                        done2 = (T2 < 1e-4f);
                    }
                }
            }
            if (__all_sync(0xffffffffu, done1 && done2)) break;
        }
        __syncthreads();   // chunk consumed before restaging
    }

    const int x  = tileX * TILE_W + lx;
    const int y1 = tileY * TILE_H + ly;
    float* o1 = out + ((size_t)y1 * IMG_W + x) * 3;
    o1[0] = r1; o1[1] = g1; o1[2] = b1;
    float* o2 = out + ((size_t)(y1 + 8) * IMG_W + x) * 3;
    o2[0] = r2; o2[1] = g2; o2[2] = b2;
}

// ---------------------------------------------------------------------------
extern "C" void kernel_launch(void* const* d_in, const int* in_sizes, int n_in,
                              void* d_out, int out_size)
{
    const float* means2d   = (const float*)d_in[0];
    const float* conics    = (const float*)d_in[1];
    const float* colors    = (const float*)d_in[2];
    const float* opacities = (const float*)d_in[3];
    const float* depths    = (const float*)d_in[4];
    float* out = (float*)d_out;

    sort_gather_kernel<<<SORT_BLOCKS, SORT_TPB>>>(means2d, conics, colors, opacities, depths);
    binning_kernel<<<G_N / ((TPB / 32) * 4), TPB>>>();
    dim3 grid(TX_N, TY_N);
    raster_kernel<<<grid, TPB>>>(out);
}